// round 4
// baseline (speedup 1.0000x reference)
#include <cuda_runtime.h>

// Performer FAVOR+ — tf32 tensor-core version (mma.sync m16n8k8).
// dash matmuls use compensated tf32 (3 passes, ~fp32 accuracy);
// E^T@V and q'@ctx use plain tf32 with RN-rounded operands.

#define BHn 128
#define Nn  4096
#define Dn  64
#define Mn  256
#define TNn 64
#define NTILES 64

#define NORMV 0.35355339059327378f   /* 64^-0.25 */
#define RATIO 0.0625f                /* 256^-0.5 */
#define EPSV  1e-4f

#define PJ_S 68    // proj_s stride
#define KQ_S 68    // k_s / q_s stride
#define VT_S 68    // vT_s stride
#define ET_S 68    // E_T stride
#define QP_S 268   // qp_s stride
#define CT_S 268   // ctxT / ctx stage stride

__device__ float g_ksum[BHn * Mn];
__device__ float g_ctxT[BHn * Dn * Mn];   // [bh][e][m]

__device__ __forceinline__ void mma8(float d[4], const unsigned a[4],
                                     const unsigned b[2]) {
  asm volatile(
      "mma.sync.aligned.m16n8k8.row.col.f32.tf32.tf32.f32 "
      "{%0,%1,%2,%3},{%4,%5,%6,%7},{%8,%9},{%0,%1,%2,%3};"
      : "+f"(d[0]), "+f"(d[1]), "+f"(d[2]), "+f"(d[3])
      : "r"(a[0]), "r"(a[1]), "r"(a[2]), "r"(a[3]), "r"(b[0]), "r"(b[1]));
}
__device__ __forceinline__ unsigned rna(float x) {
  unsigned r; asm("cvt.rna.tf32.f32 %0, %1;" : "=r"(r) : "f"(x)); return r;
}
__device__ __forceinline__ float rnaf(float x) { return __uint_as_float(rna(x)); }
__device__ __forceinline__ void split(float x, unsigned& hi, unsigned& lo) {
  hi = rna(x);
  lo = rna(x - __uint_as_float(hi));
}

// ---------------------------------------------------------------------------
// Kernel 1: K phase. One CTA per bh, 256 threads (8 warps).
// ---------------------------------------------------------------------------
__global__ __launch_bounds__(256, 1) void kphase_kernel(
    const float* __restrict__ kg, const float* __restrict__ vg,
    const float* __restrict__ projg) {
  extern __shared__ float sm[];
  float* proj_s = sm;                   // [256][68]
  float* k_s    = proj_s + 256 * PJ_S;  // [64][68]
  float* vT_s   = k_s + 64 * KQ_S;      // [64][68]  (tf32-rounded V^T)
  float* E_T    = vT_s + 64 * VT_S;     // [256][68] (later: ctx stage [64][268])
  float* diag_s = E_T + 256 * ET_S;     // [64]
  float* red_s  = diag_s + 64;          // [64]
  float* vsum_s = red_s + 64;           // [64]

  const int bh = blockIdx.x, tid = threadIdx.x;
  const int lane = tid & 31, wid = tid >> 5;
  const int gid = lane >> 2, tig = lane & 3;
  const int m0 = wid * 32;              // warp's m-slice

  const float4* kb4 = (const float4*)(kg + (size_t)bh * Nn * Dn);
  const float4* vb4 = (const float4*)(vg + (size_t)bh * Nn * Dn);

  for (int i = tid; i < 4096; i += 256) {
    float4 p = ((const float4*)projg)[i];
    *(float4*)&proj_s[(i >> 4) * PJ_S + (i & 15) * 4] = p;
  }

  float C2[2][8][4];
#pragma unroll
  for (int g = 0; g < 2; g++)
#pragma unroll
    for (int e = 0; e < 8; e++)
#pragma unroll
      for (int j = 0; j < 4; j++) C2[g][e][j] = 0.f;
  float uacc[4][2] = {};
  float vsum = 0.f, dmax = -1e30f;

  for (int t = 0; t < NTILES; t++) {
    __syncthreads();  // protect k_s/vT_s (+ proj on iter 0)
    for (int i = tid; i < 1024; i += 256) {
      int r = i >> 4, c4 = (i & 15) * 4;
      float4 kv = kb4[t * 1024 + i];
      kv.x *= NORMV; kv.y *= NORMV; kv.z *= NORMV; kv.w *= NORMV;
      *(float4*)&k_s[r * KQ_S + c4] = kv;
      float4 vv = vb4[t * 1024 + i];
      vT_s[(c4 + 0) * VT_S + r] = rnaf(vv.x);
      vT_s[(c4 + 1) * VT_S + r] = rnaf(vv.y);
      vT_s[(c4 + 2) * VT_S + r] = rnaf(vv.z);
      vT_s[(c4 + 3) * VT_S + r] = rnaf(vv.w);
    }
    __syncthreads();

    if (tid < 64) {
      float s = 0.f;
#pragma unroll
      for (int d4 = 0; d4 < 16; d4++) {
        float4 x = *(const float4*)&k_s[tid * KQ_S + d4 * 4];
        s += x.x * x.x + x.y * x.y + x.z * x.z + x.w * x.w;
      }
      diag_s[tid] = 0.5f * s;
      float vs = 0.f;
#pragma unroll 8
      for (int r = 0; r < 64; r++) vs += vT_s[tid * VT_S + r];
      vsum += vs;
    }

    // ---- dash = k @ proj^T  (compensated tf32) ----
    float dfrag[4][4][4];
#pragma unroll
    for (int g = 0; g < 4; g++)
#pragma unroll
      for (int mt = 0; mt < 4; mt++)
#pragma unroll
        for (int j = 0; j < 4; j++) dfrag[g][mt][j] = 0.f;

#pragma unroll
    for (int ks = 0; ks < 8; ks++) {
      unsigned ahi[4][4], alo[4][4];
#pragma unroll
      for (int g = 0; g < 4; g++) {
        int r = g * 16 + gid;
        split(k_s[r * KQ_S + ks * 8 + tig], ahi[g][0], alo[g][0]);
        split(k_s[(r + 8) * KQ_S + ks * 8 + tig], ahi[g][1], alo[g][1]);
        split(k_s[r * KQ_S + ks * 8 + tig + 4], ahi[g][2], alo[g][2]);
        split(k_s[(r + 8) * KQ_S + ks * 8 + tig + 4], ahi[g][3], alo[g][3]);
      }
#pragma unroll
      for (int mt = 0; mt < 4; mt++) {
        unsigned bhi[2], blo[2];
        int n = m0 + mt * 8 + gid;
        split(proj_s[n * PJ_S + ks * 8 + tig], bhi[0], blo[0]);
        split(proj_s[n * PJ_S + ks * 8 + tig + 4], bhi[1], blo[1]);
#pragma unroll
        for (int g = 0; g < 4; g++) {
          mma8(dfrag[g][mt], alo[g], bhi);
          mma8(dfrag[g][mt], ahi[g], blo);
          mma8(dfrag[g][mt], ahi[g], bhi);
        }
      }
    }
    __syncthreads();  // diag_s ready; E_T free (prev matmul2 done)

    // ---- exp, write E^T, accumulate U and max ----
#pragma unroll
    for (int g = 0; g < 4; g++) {
      int r = g * 16 + gid;
      float dg0 = diag_s[r], dg1 = diag_s[r + 8];
#pragma unroll
      for (int mt = 0; mt < 4; mt++) {
        int m = m0 + mt * 8 + 2 * tig;
        float d0 = dfrag[g][mt][0], d1 = dfrag[g][mt][1];
        float d2 = dfrag[g][mt][2], d3 = dfrag[g][mt][3];
        dmax = fmaxf(dmax, fmaxf(fmaxf(d0, d1), fmaxf(d2, d3)));
        float e0 = __expf(d0 - dg0), e1 = __expf(d1 - dg0);
        float e2 = __expf(d2 - dg1), e3 = __expf(d3 - dg1);
        uacc[mt][0] += e0 + e2;
        uacc[mt][1] += e1 + e3;
        E_T[m * ET_S + r]           = rnaf(e0);
        E_T[(m + 1) * ET_S + r]     = rnaf(e1);
        E_T[m * ET_S + r + 8]       = rnaf(e2);
        E_T[(m + 1) * ET_S + r + 8] = rnaf(e3);
      }
    }
    __syncthreads();  // E_T ready

    // ---- C2 += E^T(m-slice) @ V  (plain tf32) ----
#pragma unroll
    for (int ks = 0; ks < 8; ks++) {
      unsigned a[2][4];
#pragma unroll
      for (int g2 = 0; g2 < 2; g2++) {
        int mr = m0 + g2 * 16 + gid;
        a[g2][0] = __float_as_uint(E_T[mr * ET_S + ks * 8 + tig]);
        a[g2][1] = __float_as_uint(E_T[(mr + 8) * ET_S + ks * 8 + tig]);
        a[g2][2] = __float_as_uint(E_T[mr * ET_S + ks * 8 + tig + 4]);
        a[g2][3] = __float_as_uint(E_T[(mr + 8) * ET_S + ks * 8 + tig + 4]);
      }
#pragma unroll
      for (int et = 0; et < 8; et++) {
        unsigned b[2];
        int e = et * 8 + gid;
        b[0] = __float_as_uint(vT_s[e * VT_S + ks * 8 + tig]);
        b[1] = __float_as_uint(vT_s[e * VT_S + ks * 8 + tig + 4]);
        mma8(C2[0][et], a[0], b);
        mma8(C2[1][et], a[1], b);
      }
    }
  }

  // ---- finalize ----
  float wm = dmax;
#pragma unroll
  for (int off = 16; off; off >>= 1)
    wm = fmaxf(wm, __shfl_xor_sync(0xffffffffu, wm, off));
  if (lane == 0) red_s[wid] = wm;
  if (tid < 64) vsum_s[tid] = vsum;
  __syncthreads();
  if (tid == 0) {
    float mm = red_s[0];
#pragma unroll
    for (int w = 1; w < 8; w++) mm = fmaxf(mm, red_s[w]);
    red_s[8] = mm;
  }
  __syncthreads();
  const float scale = __expf(-red_s[8]);

  // ksum (U reduced over row-group lanes)
#pragma unroll
  for (int mt = 0; mt < 4; mt++) {
#pragma unroll
    for (int j = 0; j < 2; j++) {
      float u = uacc[mt][j];
      u += __shfl_xor_sync(0xffffffffu, u, 4);
      u += __shfl_xor_sync(0xffffffffu, u, 8);
      u += __shfl_xor_sync(0xffffffffu, u, 16);
      if (gid == 0)
        g_ksum[bh * Mn + m0 + mt * 8 + 2 * tig + j] =
            RATIO * (scale * u + EPSV * (float)Nn);
    }
  }

  // ctx -> stage (reuse E_T) -> global (transposed layout [e][m])
  float* stage = E_T;
#pragma unroll
  for (int g2 = 0; g2 < 2; g2++) {
    int m = m0 + g2 * 16 + gid;
#pragma unroll
    for (int et = 0; et < 8; et++) {
      int e = et * 8 + 2 * tig;
      stage[e * CT_S + m]           = RATIO * (scale * C2[g2][et][0] + EPSV * vsum_s[e]);
      stage[(e + 1) * CT_S + m]     = RATIO * (scale * C2[g2][et][1] + EPSV * vsum_s[e + 1]);
      stage[e * CT_S + m + 8]       = RATIO * (scale * C2[g2][et][2] + EPSV * vsum_s[e]);
      stage[(e + 1) * CT_S + m + 8] = RATIO * (scale * C2[g2][et][3] + EPSV * vsum_s[e + 1]);
    }
  }
  __syncthreads();
  float* cg = g_ctxT + (size_t)bh * Dn * Mn;
  for (int i = tid; i < 4096; i += 256) {
    int e = i >> 6, m4 = (i & 63) * 4;
    *(float4*)&cg[e * Mn + m4] = *(const float4*)&stage[e * CT_S + m4];
  }
}

// ---------------------------------------------------------------------------
// Kernel 2: Q phase. grid (64 tiles, 128 bh), 256 threads.
// ---------------------------------------------------------------------------
__global__ __launch_bounds__(256, 1) void qphase_kernel(
    const float* __restrict__ qg, const float* __restrict__ projg,
    float* __restrict__ outg) {
  extern __shared__ float sm[];
  float* unionA = sm;                   // proj [256][68] -> ctxT [64][268]
  float* q_s    = unionA + 256 * PJ_S;  // [64][68]
  float* qp_s   = q_s + 64 * KQ_S;      // [64][268]
  float* ksum_s = qp_s + 64 * QP_S;     // [256]
  float* diag_s = ksum_s + 256;         // [64]
  float* rmax_s = diag_s + 64;          // [64][8]
  float* denom_s = rmax_s + 512;        // [64]

  const int bh = blockIdx.y, tile = blockIdx.x, tid = threadIdx.x;
  const int lane = tid & 31, wid = tid >> 5;
  const int gid = lane >> 2, tig = lane & 3;
  const int m0 = wid * 32;

  const float4* qt4 =
      (const float4*)(qg + ((size_t)bh * Nn + (size_t)tile * TNn) * Dn);

  for (int i = tid; i < 4096; i += 256) {
    float4 p = ((const float4*)projg)[i];
    *(float4*)&unionA[(i >> 4) * PJ_S + (i & 15) * 4] = p;
  }
  for (int i = tid; i < 1024; i += 256) {
    float4 qv = qt4[i];
    qv.x *= NORMV; qv.y *= NORMV; qv.z *= NORMV; qv.w *= NORMV;
    *(float4*)&q_s[(i >> 4) * KQ_S + (i & 15) * 4] = qv;
  }
  ksum_s[tid] = g_ksum[bh * Mn + tid];
  __syncthreads();

  if (tid < 64) {
    float s = 0.f;
#pragma unroll
    for (int d4 = 0; d4 < 16; d4++) {
      float4 x = *(const float4*)&q_s[tid * KQ_S + d4 * 4];
      s += x.x * x.x + x.y * x.y + x.z * x.z + x.w * x.w;
    }
    diag_s[tid] = 0.5f * s;
  }

  // ---- dash = q @ proj^T (compensated tf32) ----
  float dfrag[4][4][4];
#pragma unroll
  for (int g = 0; g < 4; g++)
#pragma unroll
    for (int mt = 0; mt < 4; mt++)
#pragma unroll
      for (int j = 0; j < 4; j++) dfrag[g][mt][j] = 0.f;

#pragma unroll
  for (int ks = 0; ks < 8; ks++) {
    unsigned ahi[4][4], alo[4][4];
#pragma unroll
    for (int g = 0; g < 4; g++) {
      int r = g * 16 + gid;
      split(q_s[r * KQ_S + ks * 8 + tig], ahi[g][0], alo[g][0]);
      split(q_s[(r + 8) * KQ_S + ks * 8 + tig], ahi[g][1], alo[g][1]);
      split(q_s[r * KQ_S + ks * 8 + tig + 4], ahi[g][2], alo[g][2]);
      split(q_s[(r + 8) * KQ_S + ks * 8 + tig + 4], ahi[g][3], alo[g][3]);
    }
#pragma unroll
    for (int mt = 0; mt < 4; mt++) {
      unsigned bhi[2], blo[2];
      int n = m0 + mt * 8 + gid;
      split(unionA[n * PJ_S + ks * 8 + tig], bhi[0], blo[0]);
      split(unionA[n * PJ_S + ks * 8 + tig + 4], bhi[1], blo[1]);
#pragma unroll
      for (int g = 0; g < 4; g++) {
        mma8(dfrag[g][mt], alo[g], bhi);
        mma8(dfrag[g][mt], ahi[g], blo);
        mma8(dfrag[g][mt], ahi[g], bhi);
      }
    }
  }

  // per-warp row-max partials (over this warp's 32 m-cols)
#pragma unroll
  for (int g = 0; g < 4; g++) {
    float mlo = -1e30f, mhi = -1e30f;
#pragma unroll
    for (int mt = 0; mt < 4; mt++) {
      mlo = fmaxf(mlo, fmaxf(dfrag[g][mt][0], dfrag[g][mt][1]));
      mhi = fmaxf(mhi, fmaxf(dfrag[g][mt][2], dfrag[g][mt][3]));
    }
    mlo = fmaxf(mlo, __shfl_xor_sync(0xffffffffu, mlo, 1));
    mlo = fmaxf(mlo, __shfl_xor_sync(0xffffffffu, mlo, 2));
    mhi = fmaxf(mhi, __shfl_xor_sync(0xffffffffu, mhi, 1));
    mhi = fmaxf(mhi, __shfl_xor_sync(0xffffffffu, mhi, 2));
    if (tig == 0) {
      rmax_s[(g * 16 + gid) * 8 + wid] = mlo;
      rmax_s[(g * 16 + gid + 8) * 8 + wid] = mhi;
    }
  }
  __syncthreads();  // rmax + diag ready

  // ---- q' = ratio*(exp(dash - diag - rowmax) + eps), write row-major ----
#pragma unroll
  for (int g = 0; g < 4; g++) {
    int r = g * 16 + gid;
    float r0 = rmax_s[r * 8], r1 = rmax_s[(r + 8) * 8];
#pragma unroll
    for (int w = 1; w < 8; w++) {
      r0 = fmaxf(r0, rmax_s[r * 8 + w]);
      r1 = fmaxf(r1, rmax_s[(r + 8) * 8 + w]);
    }
    float sub0 = diag_s[r] + r0, sub1 = diag_s[r + 8] + r1;
#pragma unroll
    for (int mt = 0; mt < 4; mt++) {
      int m = m0 + mt * 8 + 2 * tig;
      float q0 = RATIO * (__expf(dfrag[g][mt][0] - sub0) + EPSV);
      float q1 = RATIO * (__expf(dfrag[g][mt][1] - sub0) + EPSV);
      float q2 = RATIO * (__expf(dfrag[g][mt][2] - sub1) + EPSV);
      float q3 = RATIO * (__expf(dfrag[g][mt][3] - sub1) + EPSV);
      qp_s[r * QP_S + m]           = rnaf(q0);
      qp_s[r * QP_S + m + 1]       = rnaf(q1);
      qp_s[(r + 8) * QP_S + m]     = rnaf(q2);
      qp_s[(r + 8) * QP_S + m + 1] = rnaf(q3);
    }
  }
  __syncthreads();  // qp ready; proj no longer needed

  // overlay ctxT into unionA (tf32-rounded)
  {
    const float4* cg = (const float4*)(g_ctxT + (size_t)bh * Dn * Mn);
    for (int i = tid; i < 4096; i += 256) {
      float4 c = cg[i];
      int e = i >> 6, m4 = (i & 63) * 4;
      unionA[e * CT_S + m4]     = rnaf(c.x);
      unionA[e * CT_S + m4 + 1] = rnaf(c.y);
      unionA[e * CT_S + m4 + 2] = rnaf(c.z);
      unionA[e * CT_S + m4 + 3] = rnaf(c.w);
    }
  }
  // denom[r] = sum_m qp[r][m] * ksum[m]
  {
    int r = tid >> 2, qq = tid & 3;
    float s = 0.f;
#pragma unroll 8
    for (int i = 0; i < 64; i++) {
      int m = qq * 64 + i;
      s += qp_s[r * QP_S + m] * ksum_s[m];
    }
    s += __shfl_xor_sync(0xffffffffu, s, 1);
    s += __shfl_xor_sync(0xffffffffu, s, 2);
    if (qq == 0) denom_s[r] = s;
  }
  __syncthreads();

  // ---- out = (q' @ ctx) / denom  (plain tf32) ----
  const int rg = (wid & 3) * 16;
  const int eh = (wid >> 2) * 32;
  float ofrag[4][4];
#pragma unroll
  for (int et = 0; et < 4; et++)
#pragma unroll
    for (int j = 0; j < 4; j++) ofrag[et][j] = 0.f;

#pragma unroll 4
  for (int ks = 0; ks < 32; ks++) {
    unsigned a[4];
    a[0] = __float_as_uint(qp_s[(rg + gid) * QP_S + ks * 8 + tig]);
    a[1] = __float_as_uint(qp_s[(rg + gid + 8) * QP_S + ks * 8 + tig]);
    a[2] = __float_as_uint(qp_s[(rg + gid) * QP_S + ks * 8 + tig + 4]);
    a[3] = __float_as_uint(qp_s[(rg + gid + 8) * QP_S + ks * 8 + tig + 4]);
#pragma unroll
    for (int et = 0; et < 4; et++) {
      unsigned b[2];
      int e = eh + et * 8 + gid;
      b[0] = __float_as_uint(unionA[e * CT_S + ks * 8 + tig]);
      b[1] = __float_as_uint(unionA[e * CT_S + ks * 8 + tig + 4]);
      mma8(ofrag[et], a, b);
    }
  }

  float inv0 = 1.f / denom_s[rg + gid];
  float inv1 = 1.f / denom_s[rg + gid + 8];
  float* ob = outg + ((size_t)bh * Nn + (size_t)tile * TNn) * Dn;
#pragma unroll
  for (int et = 0; et < 4; et++) {
    int e = eh + et * 8 + 2 * tig;
    int r = rg + gid;
    *(float2*)&ob[r * Dn + e] =
        make_float2(ofrag[et][0] * inv0, ofrag[et][1] * inv0);
    *(float2*)&ob[(r + 8) * Dn + e] =
        make_float2(ofrag[et][2] * inv1, ofrag[et][3] * inv1);
  }
}

// ---------------------------------------------------------------------------
extern "C" void kernel_launch(void* const* d_in, const int* in_sizes, int n_in,
                              void* d_out, int out_size) {
  const float* q    = (const float*)d_in[0];
  const float* k    = (const float*)d_in[1];
  const float* v    = (const float*)d_in[2];
  const float* proj = (const float*)d_in[3];
  float* out = (float*)d_out;

  const int smem1 = (256 * PJ_S + 64 * KQ_S + 64 * VT_S + 256 * ET_S + 192) * 4;
  const int smem2 =
      (256 * PJ_S + 64 * KQ_S + 64 * QP_S + 256 + 64 + 512 + 64) * 4;

  cudaFuncSetAttribute(kphase_kernel, cudaFuncAttributeMaxDynamicSharedMemorySize, smem1);
  cudaFuncSetAttribute(qphase_kernel, cudaFuncAttributeMaxDynamicSharedMemorySize, smem2);

  kphase_kernel<<<BHn, 256, smem1>>>(k, v, proj);
  qphase_kernel<<<dim3(NTILES, BHn), 256, smem2>>>(q, proj, out);
}

// round 5
// speedup vs baseline: 1.8816x; 1.8816x over previous
#include <cuda_runtime.h>

// Performer FAVOR+ — tf32 mma.sync + ldmatrix, 512-thread CTAs.
// dash: 2-pass compensated tf32 (A split hi/lo, B rounded once).
// E^T@V and q'@ctx: plain tf32, RN-rounded operands.

#define BHn 128
#define Nn  4096
#define Dn  64
#define Mn  256
#define TNn 64
#define NTILES 64

#define NORMV 0.35355339059327378f
#define RATIO 0.0625f
#define EPSV  1e-4f

#define PJ_S 68
#define KQ_S 68
#define VT_S 68
#define ET_S 68
#define QP_S 268
#define CT_S 268

__device__ float g_ksum[BHn * Mn];
__device__ float g_ctxT[BHn * Dn * Mn];   // [bh][e][m]

__device__ __forceinline__ void mma8(float d[4], const unsigned a[4],
                                     const unsigned b[2]) {
  asm volatile(
      "mma.sync.aligned.m16n8k8.row.col.f32.tf32.tf32.f32 "
      "{%0,%1,%2,%3},{%4,%5,%6,%7},{%8,%9},{%0,%1,%2,%3};"
      : "+f"(d[0]), "+f"(d[1]), "+f"(d[2]), "+f"(d[3])
      : "r"(a[0]), "r"(a[1]), "r"(a[2]), "r"(a[3]), "r"(b[0]), "r"(b[1]));
}
__device__ __forceinline__ void ldsm4(unsigned r[4], unsigned addr) {
  asm volatile(
      "ldmatrix.sync.aligned.m8n8.x4.shared.b16 {%0,%1,%2,%3}, [%4];"
      : "=r"(r[0]), "=r"(r[1]), "=r"(r[2]), "=r"(r[3]) : "r"(addr));
}
__device__ __forceinline__ unsigned rna(float x) {
  unsigned r; asm("cvt.rna.tf32.f32 %0, %1;" : "=r"(r) : "f"(x)); return r;
}
__device__ __forceinline__ float rnaf(float x) { return __uint_as_float(rna(x)); }
__device__ __forceinline__ unsigned s2u(const void* p) {
  return (unsigned)__cvta_generic_to_shared(p);
}

// lane-offset (in floats) for A-style fragments: tiles {rows0-8/lo, rows8-16/lo,
// rows0-8/hi, rows8-16/hi}; and B-style: {n0/lo, n0/hi, n1/lo, n1/hi}.
__device__ __forceinline__ int a_off(int lane, int S) {
  return (((lane >> 3) & 1) * 8 + (lane & 7)) * S + (lane >> 4) * 4;
}
__device__ __forceinline__ int b_off(int lane, int S) {
  return ((lane >> 4) * 8 + (lane & 7)) * S + ((lane >> 3) & 1) * 4;
}

// ---------------------------------------------------------------------------
// Kernel 1: K phase. One CTA per bh, 512 threads (16 warps).
// ---------------------------------------------------------------------------
__global__ __launch_bounds__(512, 1) void kphase_kernel(
    const float* __restrict__ kg, const float* __restrict__ vg,
    const float* __restrict__ projg) {
  extern __shared__ float sm[];
  float* proj_s = sm;                   // [256][68]  rna-rounded
  float* k_hi   = proj_s + 256 * PJ_S;  // [64][68]
  float* k_lo   = k_hi + 64 * KQ_S;     // [64][68]
  float* vT_s   = k_lo + 64 * KQ_S;     // [64][68]  rna
  float* E_T    = vT_s + 64 * VT_S;     // [256][68] rna; reused as ctx stage
  float* diag_s = E_T + 256 * ET_S;     // [64]
  float* red_s  = diag_s + 64;          // [64]
  float* vsum_s = red_s + 64;           // [64]

  const int bh = blockIdx.x, tid = threadIdx.x;
  const int lane = tid & 31, wid = tid >> 5;
  const int gid = lane >> 2, tig = lane & 3;
  const int m0 = wid * 16;

  const unsigned u_proj = s2u(proj_s), u_khi = s2u(k_hi), u_klo = s2u(k_lo);
  const unsigned u_vT = s2u(vT_s), u_ET = s2u(E_T);
  const int aoKQ = a_off(lane, KQ_S), boPJ = b_off(lane, PJ_S);
  const int aoET = a_off(lane, ET_S), boVT = b_off(lane, VT_S);

  const float4* kb4 = (const float4*)(kg + (size_t)bh * Nn * Dn);
  const float4* vb4 = (const float4*)(vg + (size_t)bh * Nn * Dn);

  for (int i = tid; i < 4096; i += 512) {
    float4 p = ((const float4*)projg)[i];
    p.x = rnaf(p.x); p.y = rnaf(p.y); p.z = rnaf(p.z); p.w = rnaf(p.w);
    *(float4*)&proj_s[(i >> 4) * PJ_S + (i & 15) * 4] = p;
  }

  float C2[8][4];
#pragma unroll
  for (int e = 0; e < 8; e++)
#pragma unroll
    for (int j = 0; j < 4; j++) C2[e][j] = 0.f;
  float uacc[2][2] = {};
  float vsum = 0.f, dmax = -1e30f;

  for (int t = 0; t < NTILES; t++) {
    __syncthreads();
    for (int i = tid; i < 1024; i += 512) {
      int r = i >> 4, c4 = (i & 15) * 4;
      float4 kv = kb4[t * 1024 + i];
      kv.x *= NORMV; kv.y *= NORMV; kv.z *= NORMV; kv.w *= NORMV;
      float4 hi, lo;
      hi.x = rnaf(kv.x); lo.x = kv.x - hi.x;
      hi.y = rnaf(kv.y); lo.y = kv.y - hi.y;
      hi.z = rnaf(kv.z); lo.z = kv.z - hi.z;
      hi.w = rnaf(kv.w); lo.w = kv.w - hi.w;
      *(float4*)&k_hi[r * KQ_S + c4] = hi;
      *(float4*)&k_lo[r * KQ_S + c4] = lo;
      float4 vv = vb4[t * 1024 + i];
      vT_s[(c4 + 0) * VT_S + r] = rnaf(vv.x);
      vT_s[(c4 + 1) * VT_S + r] = rnaf(vv.y);
      vT_s[(c4 + 2) * VT_S + r] = rnaf(vv.z);
      vT_s[(c4 + 3) * VT_S + r] = rnaf(vv.w);
    }
    __syncthreads();

    if (tid < 64) {
      float s = 0.f;
#pragma unroll
      for (int d4 = 0; d4 < 16; d4++) {
        float4 h = *(const float4*)&k_hi[tid * KQ_S + d4 * 4];
        float4 l = *(const float4*)&k_lo[tid * KQ_S + d4 * 4];
        float x0 = h.x + l.x, x1 = h.y + l.y, x2 = h.z + l.z, x3 = h.w + l.w;
        s += x0 * x0 + x1 * x1 + x2 * x2 + x3 * x3;
      }
      diag_s[tid] = 0.5f * s;
      float vs = 0.f;
#pragma unroll 8
      for (int r = 0; r < 64; r++) vs += vT_s[tid * VT_S + r];
      vsum += vs;
    }

    // ---- dash = k @ proj^T (2-pass compensated tf32) ----
    float dfrag[4][2][4];
#pragma unroll
    for (int g = 0; g < 4; g++)
#pragma unroll
      for (int mt = 0; mt < 2; mt++)
#pragma unroll
        for (int j = 0; j < 4; j++) dfrag[g][mt][j] = 0.f;

#pragma unroll
    for (int ks = 0; ks < 8; ks++) {
      unsigned bf[4];
      ldsm4(bf, u_proj + (unsigned)(m0 * PJ_S + ks * 8 + boPJ) * 4u);
#pragma unroll
      for (int g = 0; g < 4; g++) {
        unsigned ah[4], al[4];
        ldsm4(ah, u_khi + (unsigned)(g * 16 * KQ_S + ks * 8 + aoKQ) * 4u);
        ldsm4(al, u_klo + (unsigned)(g * 16 * KQ_S + ks * 8 + aoKQ) * 4u);
        mma8(dfrag[g][0], ah, bf);
        mma8(dfrag[g][0], al, bf);
        mma8(dfrag[g][1], ah, bf + 2);
        mma8(dfrag[g][1], al, bf + 2);
      }
    }
    __syncthreads();  // diag ready; E_T free

    // ---- exp, write E^T, accumulate U and max ----
#pragma unroll
    for (int g = 0; g < 4; g++) {
      int r = g * 16 + gid;
      float dg0 = diag_s[r], dg1 = diag_s[r + 8];
#pragma unroll
      for (int mt = 0; mt < 2; mt++) {
        int m = m0 + mt * 8 + 2 * tig;
        float d0 = dfrag[g][mt][0], d1 = dfrag[g][mt][1];
        float d2 = dfrag[g][mt][2], d3 = dfrag[g][mt][3];
        dmax = fmaxf(dmax, fmaxf(fmaxf(d0, d1), fmaxf(d2, d3)));
        float e0 = __expf(d0 - dg0), e1 = __expf(d1 - dg0);
        float e2 = __expf(d2 - dg1), e3 = __expf(d3 - dg1);
        uacc[mt][0] += e0 + e2;
        uacc[mt][1] += e1 + e3;
        E_T[m * ET_S + r]           = rnaf(e0);
        E_T[(m + 1) * ET_S + r]     = rnaf(e1);
        E_T[m * ET_S + r + 8]       = rnaf(e2);
        E_T[(m + 1) * ET_S + r + 8] = rnaf(e3);
      }
    }
    __syncthreads();  // E_T ready

    // ---- C2 += E^T(m-slice 16) @ V (plain tf32) ----
#pragma unroll
    for (int ks = 0; ks < 8; ks++) {
      unsigned a[4];
      ldsm4(a, u_ET + (unsigned)(m0 * ET_S + ks * 8 + aoET) * 4u);
#pragma unroll
      for (int ep = 0; ep < 4; ep++) {
        unsigned b[4];
        ldsm4(b, u_vT + (unsigned)(ep * 16 * VT_S + ks * 8 + boVT) * 4u);
        mma8(C2[ep * 2], a, b);
        mma8(C2[ep * 2 + 1], a, b + 2);
      }
    }
  }

  // ---- finalize ----
  float wm = dmax;
#pragma unroll
  for (int off = 16; off; off >>= 1)
    wm = fmaxf(wm, __shfl_xor_sync(0xffffffffu, wm, off));
  if (lane == 0) red_s[wid] = wm;
  if (tid < 64) vsum_s[tid] = vsum;
  __syncthreads();
  if (tid == 0) {
    float mm = red_s[0];
#pragma unroll
    for (int w = 1; w < 16; w++) mm = fmaxf(mm, red_s[w]);
    red_s[16] = mm;
  }
  __syncthreads();
  const float scale = __expf(-red_s[16]);

#pragma unroll
  for (int mt = 0; mt < 2; mt++) {
#pragma unroll
    for (int j = 0; j < 2; j++) {
      float u = uacc[mt][j];
      u += __shfl_xor_sync(0xffffffffu, u, 4);
      u += __shfl_xor_sync(0xffffffffu, u, 8);
      u += __shfl_xor_sync(0xffffffffu, u, 16);
      if (gid == 0)
        g_ksum[bh * Mn + m0 + mt * 8 + 2 * tig + j] =
            RATIO * (scale * u + EPSV * (float)Nn);
    }
  }

  // ctx -> stage (reuse E_T as [64][268]) -> global [e][m]
  float* stage = E_T;
  {
    int m = m0 + gid;
#pragma unroll
    for (int et = 0; et < 8; et++) {
      int e = et * 8 + 2 * tig;
      stage[e * CT_S + m]           = RATIO * (scale * C2[et][0] + EPSV * vsum_s[e]);
      stage[(e + 1) * CT_S + m]     = RATIO * (scale * C2[et][1] + EPSV * vsum_s[e + 1]);
      stage[e * CT_S + m + 8]       = RATIO * (scale * C2[et][2] + EPSV * vsum_s[e]);
      stage[(e + 1) * CT_S + m + 8] = RATIO * (scale * C2[et][3] + EPSV * vsum_s[e + 1]);
    }
  }
  __syncthreads();
  float* cg = g_ctxT + (size_t)bh * Dn * Mn;
  for (int i = tid; i < 4096; i += 512) {
    int e = i >> 6, m4 = (i & 63) * 4;
    *(float4*)&cg[e * Mn + m4] = *(const float4*)&stage[e * CT_S + m4];
  }
}

// ---------------------------------------------------------------------------
// Kernel 2: Q phase. grid (64 tiles, 128 bh), 512 threads (16 warps).
// ---------------------------------------------------------------------------
__global__ __launch_bounds__(512, 1) void qphase_kernel(
    const float* __restrict__ qg, const float* __restrict__ projg,
    float* __restrict__ outg) {
  extern __shared__ float sm[];
  float* unionA = sm;                   // proj [256][68] -> ctxT [64][268]
  float* q_hi   = unionA + 256 * PJ_S;  // [64][68]
  float* q_lo   = q_hi + 64 * KQ_S;     // [64][68]
  float* qp_s   = q_lo + 64 * KQ_S;     // [64][268]
  float* ksum_s = qp_s + 64 * QP_S;     // [256]
  float* diag_s = ksum_s + 256;         // [64]
  float* rmax_s = diag_s + 64;          // [64][16]
  float* denom_s = rmax_s + 1024;       // [64]

  const int bh = blockIdx.y, tile = blockIdx.x, tid = threadIdx.x;
  const int lane = tid & 31, wid = tid >> 5;
  const int gid = lane >> 2, tig = lane & 3;
  const int m0 = wid * 16;

  const unsigned u_A = s2u(unionA), u_qhi = s2u(q_hi), u_qlo = s2u(q_lo);
  const unsigned u_qp = s2u(qp_s);
  const int aoKQ = a_off(lane, KQ_S), boPJ = b_off(lane, PJ_S);
  const int aoQP = a_off(lane, QP_S), boCT = b_off(lane, CT_S);

  const float4* qt4 =
      (const float4*)(qg + ((size_t)bh * Nn + (size_t)tile * TNn) * Dn);

  for (int i = tid; i < 4096; i += 512) {
    float4 p = ((const float4*)projg)[i];
    p.x = rnaf(p.x); p.y = rnaf(p.y); p.z = rnaf(p.z); p.w = rnaf(p.w);
    *(float4*)&unionA[(i >> 4) * PJ_S + (i & 15) * 4] = p;
  }
  for (int i = tid; i < 1024; i += 512) {
    int r = i >> 4, c4 = (i & 15) * 4;
    float4 qv = qt4[i];
    qv.x *= NORMV; qv.y *= NORMV; qv.z *= NORMV; qv.w *= NORMV;
    float4 hi, lo;
    hi.x = rnaf(qv.x); lo.x = qv.x - hi.x;
    hi.y = rnaf(qv.y); lo.y = qv.y - hi.y;
    hi.z = rnaf(qv.z); lo.z = qv.z - hi.z;
    hi.w = rnaf(qv.w); lo.w = qv.w - hi.w;
    *(float4*)&q_hi[r * KQ_S + c4] = hi;
    *(float4*)&q_lo[r * KQ_S + c4] = lo;
  }
  if (tid < 256) ksum_s[tid] = g_ksum[bh * Mn + tid];
  __syncthreads();

  if (tid < 64) {
    float s = 0.f;
#pragma unroll
    for (int d4 = 0; d4 < 16; d4++) {
      float4 h = *(const float4*)&q_hi[tid * KQ_S + d4 * 4];
      float4 l = *(const float4*)&q_lo[tid * KQ_S + d4 * 4];
      float x0 = h.x + l.x, x1 = h.y + l.y, x2 = h.z + l.z, x3 = h.w + l.w;
      s += x0 * x0 + x1 * x1 + x2 * x2 + x3 * x3;
    }
    diag_s[tid] = 0.5f * s;
  }

  // ---- dash (2-pass compensated tf32) ----
  float dfrag[4][2][4];
#pragma unroll
  for (int g = 0; g < 4; g++)
#pragma unroll
    for (int mt = 0; mt < 2; mt++)
#pragma unroll
      for (int j = 0; j < 4; j++) dfrag[g][mt][j] = 0.f;

#pragma unroll
  for (int ks = 0; ks < 8; ks++) {
    unsigned bf[4];
    ldsm4(bf, u_A + (unsigned)(m0 * PJ_S + ks * 8 + boPJ) * 4u);
#pragma unroll
    for (int g = 0; g < 4; g++) {
      unsigned ah[4], al[4];
      ldsm4(ah, u_qhi + (unsigned)(g * 16 * KQ_S + ks * 8 + aoKQ) * 4u);
      ldsm4(al, u_qlo + (unsigned)(g * 16 * KQ_S + ks * 8 + aoKQ) * 4u);
      mma8(dfrag[g][0], ah, bf);
      mma8(dfrag[g][0], al, bf);
      mma8(dfrag[g][1], ah, bf + 2);
      mma8(dfrag[g][1], al, bf + 2);
    }
  }

  // per-warp row-max partials over this warp's 16 m-cols
#pragma unroll
  for (int g = 0; g < 4; g++) {
    float mlo = -1e30f, mhi = -1e30f;
#pragma unroll
    for (int mt = 0; mt < 2; mt++) {
      mlo = fmaxf(mlo, fmaxf(dfrag[g][mt][0], dfrag[g][mt][1]));
      mhi = fmaxf(mhi, fmaxf(dfrag[g][mt][2], dfrag[g][mt][3]));
    }
    mlo = fmaxf(mlo, __shfl_xor_sync(0xffffffffu, mlo, 1));
    mlo = fmaxf(mlo, __shfl_xor_sync(0xffffffffu, mlo, 2));
    mhi = fmaxf(mhi, __shfl_xor_sync(0xffffffffu, mhi, 1));
    mhi = fmaxf(mhi, __shfl_xor_sync(0xffffffffu, mhi, 2));
    if (tig == 0) {
      rmax_s[(g * 16 + gid) * 16 + wid] = mlo;
      rmax_s[(g * 16 + gid + 8) * 16 + wid] = mhi;
    }
  }
  __syncthreads();

  // ---- q' = ratio*(exp(dash - diag - rowmax) + eps) ----
#pragma unroll
  for (int g = 0; g < 4; g++) {
    int r = g * 16 + gid;
    float r0 = rmax_s[r * 16], r1 = rmax_s[(r + 8) * 16];
#pragma unroll
    for (int w = 1; w < 16; w++) {
      r0 = fmaxf(r0, rmax_s[r * 16 + w]);
      r1 = fmaxf(r1, rmax_s[(r + 8) * 16 + w]);
    }
    float sub0 = diag_s[r] + r0, sub1 = diag_s[r + 8] + r1;
#pragma unroll
    for (int mt = 0; mt < 2; mt++) {
      int m = m0 + mt * 8 + 2 * tig;
      qp_s[r * QP_S + m]           = rnaf(RATIO * (__expf(dfrag[g][mt][0] - sub0) + EPSV));
      qp_s[r * QP_S + m + 1]       = rnaf(RATIO * (__expf(dfrag[g][mt][1] - sub0) + EPSV));
      qp_s[(r + 8) * QP_S + m]     = rnaf(RATIO * (__expf(dfrag[g][mt][2] - sub1) + EPSV));
      qp_s[(r + 8) * QP_S + m + 1] = rnaf(RATIO * (__expf(dfrag[g][mt][3] - sub1) + EPSV));
    }
  }
  __syncthreads();  // qp ready; proj dead

  // overlay ctxT into unionA (rna)
  {
    const float4* cg = (const float4*)(g_ctxT + (size_t)bh * Dn * Mn);
    for (int i = tid; i < 4096; i += 512) {
      float4 c = cg[i];
      int e = i >> 6, m4 = (i & 63) * 4;
      unionA[e * CT_S + m4]     = rnaf(c.x);
      unionA[e * CT_S + m4 + 1] = rnaf(c.y);
      unionA[e * CT_S + m4 + 2] = rnaf(c.z);
      unionA[e * CT_S + m4 + 3] = rnaf(c.w);
    }
  }
  // denom
  if (tid < 256) {
    int r = tid >> 2, qq = tid & 3;
    float s = 0.f;
#pragma unroll 8
    for (int i = 0; i < 64; i++) {
      int m = qq * 64 + i;
      s += qp_s[r * QP_S + m] * ksum_s[m];
    }
    s += __shfl_xor_sync(0xffffffffu, s, 1);
    s += __shfl_xor_sync(0xffffffffu, s, 2);
    if (qq == 0) denom_s[r] = s;
  }
  __syncthreads();

  // ---- out = (q' @ ctx) / denom; warp = [16 r][16 e] patch ----
  const int rg = (wid & 3) * 16;
  const int eh = (wid >> 2) * 16;
  float ofrag[2][4];
#pragma unroll
  for (int et = 0; et < 2; et++)
#pragma unroll
    for (int j = 0; j < 4; j++) ofrag[et][j] = 0.f;

#pragma unroll 8
  for (int ks = 0; ks < 32; ks++) {
    unsigned a[4], b[4];
    ldsm4(a, u_qp + (unsigned)(rg * QP_S + ks * 8 + aoQP) * 4u);
    ldsm4(b, u_A + (unsigned)(eh * CT_S + ks * 8 + boCT) * 4u);
    mma8(ofrag[0], a, b);
    mma8(ofrag[1], a, b + 2);
  }

  float inv0 = 1.f / denom_s[rg + gid];
  float inv1 = 1.f / denom_s[rg + gid + 8];
  float* ob = outg + ((size_t)bh * Nn + (size_t)tile * TNn) * Dn;
#pragma unroll
  for (int et = 0; et < 2; et++) {
    int e = eh + et * 8 + 2 * tig;
    int r = rg + gid;
    *(float2*)&ob[r * Dn + e] =
        make_float2(ofrag[et][0] * inv0, ofrag[et][1] * inv0);
    *(float2*)&ob[(r + 8) * Dn + e] =
        make_float2(ofrag[et][2] * inv1, ofrag[et][3] * inv1);
  }
}

// ---------------------------------------------------------------------------
extern "C" void kernel_launch(void* const* d_in, const int* in_sizes, int n_in,
                              void* d_out, int out_size) {
  const float* q    = (const float*)d_in[0];
  const float* k    = (const float*)d_in[1];
  const float* v    = (const float*)d_in[2];
  const float* proj = (const float*)d_in[3];
  float* out = (float*)d_out;

  const int smem1 =
      (256 * PJ_S + 64 * KQ_S * 2 + 64 * VT_S + 256 * ET_S + 192) * 4;
  const int smem2 =
      (256 * PJ_S + 64 * KQ_S * 2 + 64 * QP_S + 256 + 64 + 1024 + 64) * 4;

  cudaFuncSetAttribute(kphase_kernel, cudaFuncAttributeMaxDynamicSharedMemorySize, smem1);
  cudaFuncSetAttribute(qphase_kernel, cudaFuncAttributeMaxDynamicSharedMemorySize, smem2);

  kphase_kernel<<<BHn, 512, smem1>>>(k, v, proj);
  qphase_kernel<<<dim3(NTILES, BHn), 512, smem2>>>(q, proj, out);
}

// round 6
// speedup vs baseline: 2.5842x; 1.3734x over previous
#include <cuda_runtime.h>

// Performer FAVOR+ — fused persistent kernel, tf32 mma.sync + ldmatrix.
// One CTA per (b,h): k/v pass accumulates ctx+ksum in smem, then q pass
// streams 64 q-tiles against smem-resident ctx. proj B-fragments cached
// in registers; proj smem buffer reused for E_T / q'.

#define BHn 128
#define Nn  4096
#define Dn  64
#define Mn  256
#define NTILES 64

#define NORMV 0.35355339059327378f
#define RATIO 0.0625f
#define EPSV  1e-4f

#define PJ_S 68
#define KQ_S 68
#define VT_S 68
#define ET_S 68
#define QP_S 268
#define CT_S 268

__device__ __forceinline__ void mma8(float d[4], const unsigned a[4],
                                     const unsigned b[2]) {
  asm volatile(
      "mma.sync.aligned.m16n8k8.row.col.f32.tf32.tf32.f32 "
      "{%0,%1,%2,%3},{%4,%5,%6,%7},{%8,%9},{%0,%1,%2,%3};"
      : "+f"(d[0]), "+f"(d[1]), "+f"(d[2]), "+f"(d[3])
      : "r"(a[0]), "r"(a[1]), "r"(a[2]), "r"(a[3]), "r"(b[0]), "r"(b[1]));
}
__device__ __forceinline__ void ldsm4(unsigned r[4], unsigned addr) {
  asm volatile(
      "ldmatrix.sync.aligned.m8n8.x4.shared.b16 {%0,%1,%2,%3}, [%4];"
      : "=r"(r[0]), "=r"(r[1]), "=r"(r[2]), "=r"(r[3]) : "r"(addr));
}
__device__ __forceinline__ unsigned rna(float x) {
  unsigned r; asm("cvt.rna.tf32.f32 %0, %1;" : "=r"(r) : "f"(x)); return r;
}
__device__ __forceinline__ float rnaf(float x) { return __uint_as_float(rna(x)); }
__device__ __forceinline__ unsigned s2u(const void* p) {
  return (unsigned)__cvta_generic_to_shared(p);
}
__device__ __forceinline__ int a_off(int lane, int S) {
  return (((lane >> 3) & 1) * 8 + (lane & 7)) * S + (lane >> 4) * 4;
}
__device__ __forceinline__ int b_off(int lane, int S) {
  return ((lane >> 4) * 8 + (lane & 7)) * S + ((lane >> 3) & 1) * 4;
}

// ---------------------------------------------------------------------------
__global__ __launch_bounds__(512, 1) void fused_kernel(
    const float* __restrict__ qg, const float* __restrict__ kg,
    const float* __restrict__ vg, const float* __restrict__ projg,
    float* __restrict__ outg) {
  extern __shared__ float sm[];
  float* bufP   = sm;                 // 17408: proj -> E_T (68) -> qp (268)
  float* bufC   = bufP + 17408;       // 17152: ctx [64][268]
  float* vT_s   = bufC + 17152;       // 4352
  float* kq_hi  = vT_s + 4352;        // 4352
  float* kq_lo  = kq_hi + 4352;       // 4352
  float* diag_s = kq_lo + 4352;       // 64
  float* vsum_s = diag_s + 64;        // 64
  float* red_s  = vsum_s + 64;        // 32
  float* ksum_s = red_s + 32;         // 256
  float* sub_s  = ksum_s + 256;       // 64
  float* rmx    = sub_s + 64;         // 1024 [64][16]
  float* den    = rmx + 1024;         // 1024 [64][16]
  float* denom_s = den + 1024;        // 64

  const int bh = blockIdx.x, tid = threadIdx.x;
  const int lane = tid & 31, wid = tid >> 5;
  const int gid = lane >> 2, tig = lane & 3;
  const int m0 = wid * 16;

  const unsigned u_P = s2u(bufP), u_C = s2u(bufC), u_vT = s2u(vT_s);
  const unsigned u_khi = s2u(kq_hi), u_klo = s2u(kq_lo);
  const int aoKQ = a_off(lane, KQ_S), boPJ = b_off(lane, PJ_S);
  const int aoET = a_off(lane, ET_S), boVT = b_off(lane, VT_S);
  const int aoQP = a_off(lane, QP_S), boCT = b_off(lane, CT_S);

  const float4* kb4 = (const float4*)(kg + (size_t)bh * Nn * Dn);
  const float4* vb4 = (const float4*)(vg + (size_t)bh * Nn * Dn);
  const float4* qb4 = (const float4*)(qg + (size_t)bh * Nn * Dn);

  // ---- proj -> smem (rna), extract B fragments into registers ----
  for (int i = tid; i < 4096; i += 512) {
    float4 p = ((const float4*)projg)[i];
    p.x = rnaf(p.x); p.y = rnaf(p.y); p.z = rnaf(p.z); p.w = rnaf(p.w);
    *(float4*)&bufP[(i >> 4) * PJ_S + (i & 15) * 4] = p;
  }
  __syncthreads();
  unsigned projB[8][4];
#pragma unroll
  for (int ks = 0; ks < 8; ks++)
    ldsm4(projB[ks], u_P + (unsigned)(m0 * PJ_S + ks * 8 + boPJ) * 4u);
  __syncthreads();  // all warps done reading proj; bufP free

  // =======================================================================
  // K/V pass
  // =======================================================================
  float C2[8][4];
#pragma unroll
  for (int e = 0; e < 8; e++)
#pragma unroll
    for (int j = 0; j < 4; j++) C2[e][j] = 0.f;
  float uacc[2][2] = {};
  float vsum = 0.f, dmax = -1e30f;

  float4 kpre[2], vpre[2];
  kpre[0] = kb4[tid]; kpre[1] = kb4[512 + tid];
  vpre[0] = vb4[tid]; vpre[1] = vb4[512 + tid];

  for (int t = 0; t < NTILES; t++) {
    __syncthreads();  // kq/vT/E free
#pragma unroll
    for (int u = 0; u < 2; u++) {
      int i = u * 512 + tid;
      int r = i >> 4, c4 = (i & 15) * 4;
      float4 kv = kpre[u];
      kv.x *= NORMV; kv.y *= NORMV; kv.z *= NORMV; kv.w *= NORMV;
      float4 hi, lo;
      hi.x = rnaf(kv.x); lo.x = kv.x - hi.x;
      hi.y = rnaf(kv.y); lo.y = kv.y - hi.y;
      hi.z = rnaf(kv.z); lo.z = kv.z - hi.z;
      hi.w = rnaf(kv.w); lo.w = kv.w - hi.w;
      *(float4*)&kq_hi[r * KQ_S + c4] = hi;
      *(float4*)&kq_lo[r * KQ_S + c4] = lo;
      float4 vv = vpre[u];
      vT_s[(c4 + 0) * VT_S + r] = rnaf(vv.x);
      vT_s[(c4 + 1) * VT_S + r] = rnaf(vv.y);
      vT_s[(c4 + 2) * VT_S + r] = rnaf(vv.z);
      vT_s[(c4 + 3) * VT_S + r] = rnaf(vv.w);
    }
    if (t < NTILES - 1) {
      kpre[0] = kb4[(t + 1) * 1024 + tid];
      kpre[1] = kb4[(t + 1) * 1024 + 512 + tid];
      vpre[0] = vb4[(t + 1) * 1024 + tid];
      vpre[1] = vb4[(t + 1) * 1024 + 512 + tid];
    }
    __syncthreads();

    if (tid < 64) {
      float s = 0.f;
#pragma unroll
      for (int d4 = 0; d4 < 16; d4++) {
        float4 h = *(const float4*)&kq_hi[tid * KQ_S + d4 * 4];
        float4 l = *(const float4*)&kq_lo[tid * KQ_S + d4 * 4];
        float x0 = h.x + l.x, x1 = h.y + l.y, x2 = h.z + l.z, x3 = h.w + l.w;
        s += x0 * x0 + x1 * x1 + x2 * x2 + x3 * x3;
      }
      diag_s[tid] = 0.5f * s;
      float vs = 0.f;
#pragma unroll 8
      for (int r = 0; r < 64; r++) vs += vT_s[tid * VT_S + r];
      vsum += vs;
    }

    // dash = k @ proj^T (2-pass compensated tf32, B from registers)
    float dfrag[4][2][4];
#pragma unroll
    for (int g = 0; g < 4; g++)
#pragma unroll
      for (int mt = 0; mt < 2; mt++)
#pragma unroll
        for (int j = 0; j < 4; j++) dfrag[g][mt][j] = 0.f;

#pragma unroll
    for (int ks = 0; ks < 8; ks++) {
#pragma unroll
      for (int g = 0; g < 4; g++) {
        unsigned ah[4], al[4];
        ldsm4(ah, u_khi + (unsigned)(g * 16 * KQ_S + ks * 8 + aoKQ) * 4u);
        ldsm4(al, u_klo + (unsigned)(g * 16 * KQ_S + ks * 8 + aoKQ) * 4u);
        mma8(dfrag[g][0], ah, projB[ks]);
        mma8(dfrag[g][0], al, projB[ks]);
        mma8(dfrag[g][1], ah, projB[ks] + 2);
        mma8(dfrag[g][1], al, projB[ks] + 2);
      }
    }
    __syncthreads();  // diag ready

    // exp -> E_T (bufP, stride 68); U and max
#pragma unroll
    for (int g = 0; g < 4; g++) {
      int r = g * 16 + gid;
      float dg0 = diag_s[r], dg1 = diag_s[r + 8];
#pragma unroll
      for (int mt = 0; mt < 2; mt++) {
        int m = m0 + mt * 8 + 2 * tig;
        float d0 = dfrag[g][mt][0], d1 = dfrag[g][mt][1];
        float d2 = dfrag[g][mt][2], d3 = dfrag[g][mt][3];
        dmax = fmaxf(dmax, fmaxf(fmaxf(d0, d1), fmaxf(d2, d3)));
        float e0 = __expf(d0 - dg0), e1 = __expf(d1 - dg0);
        float e2 = __expf(d2 - dg1), e3 = __expf(d3 - dg1);
        uacc[mt][0] += e0 + e2;
        uacc[mt][1] += e1 + e3;
        bufP[m * ET_S + r]           = rnaf(e0);
        bufP[(m + 1) * ET_S + r]     = rnaf(e1);
        bufP[m * ET_S + r + 8]       = rnaf(e2);
        bufP[(m + 1) * ET_S + r + 8] = rnaf(e3);
      }
    }
    __syncthreads();  // E ready

    // C2 += E^T(m-slice) @ V
#pragma unroll
    for (int ks = 0; ks < 8; ks++) {
      unsigned a[4];
      ldsm4(a, u_P + (unsigned)(m0 * ET_S + ks * 8 + aoET) * 4u);
#pragma unroll
      for (int ep = 0; ep < 4; ep++) {
        unsigned b[4];
        ldsm4(b, u_vT + (unsigned)(ep * 16 * VT_S + ks * 8 + boVT) * 4u);
        mma8(C2[ep * 2], a, b);
        mma8(C2[ep * 2 + 1], a, b + 2);
      }
    }
  }

  // ---- finalize ksum + ctx (all in smem) ----
  float wm = dmax;
#pragma unroll
  for (int off = 16; off; off >>= 1)
    wm = fmaxf(wm, __shfl_xor_sync(0xffffffffu, wm, off));
  if (lane == 0) red_s[wid] = wm;
  if (tid < 64) vsum_s[tid] = vsum;
  __syncthreads();
  if (tid == 0) {
    float mm = red_s[0];
#pragma unroll
    for (int w = 1; w < 16; w++) mm = fmaxf(mm, red_s[w]);
    red_s[16] = mm;
  }
  __syncthreads();
  const float scale = __expf(-red_s[16]);

#pragma unroll
  for (int mt = 0; mt < 2; mt++) {
#pragma unroll
    for (int j = 0; j < 2; j++) {
      float u = uacc[mt][j];
      u += __shfl_xor_sync(0xffffffffu, u, 4);
      u += __shfl_xor_sync(0xffffffffu, u, 8);
      u += __shfl_xor_sync(0xffffffffu, u, 16);
      if (gid == 0)
        ksum_s[m0 + mt * 8 + 2 * tig + j] =
            RATIO * (scale * u + EPSV * (float)Nn);
    }
  }

  {
    int m = m0 + gid;
#pragma unroll
    for (int et = 0; et < 8; et++) {
      int e = et * 8 + 2 * tig;
      bufC[e * CT_S + m]           = rnaf(RATIO * (scale * C2[et][0] + EPSV * vsum_s[e]));
      bufC[(e + 1) * CT_S + m]     = rnaf(RATIO * (scale * C2[et][1] + EPSV * vsum_s[e + 1]));
      bufC[e * CT_S + m + 8]       = rnaf(RATIO * (scale * C2[et][2] + EPSV * vsum_s[e]));
      bufC[(e + 1) * CT_S + m + 8] = rnaf(RATIO * (scale * C2[et][3] + EPSV * vsum_s[e + 1]));
    }
  }
  __syncthreads();  // ctx + ksum ready

  // =======================================================================
  // Q pass: 64 tiles against smem-resident ctx
  // =======================================================================
  float ksv[2][2];
#pragma unroll
  for (int mt = 0; mt < 2; mt++) {
    ksv[mt][0] = ksum_s[m0 + mt * 8 + 2 * tig];
    ksv[mt][1] = ksum_s[m0 + mt * 8 + 2 * tig + 1];
  }
  const int rg = (wid & 3) * 16;
  const int eh = (wid >> 2) * 16;

  float4 qpre[2];
  qpre[0] = qb4[tid]; qpre[1] = qb4[512 + tid];

  for (int t = 0; t < NTILES; t++) {
    __syncthreads();  // kq + bufP(qp) free
#pragma unroll
    for (int u = 0; u < 2; u++) {
      int i = u * 512 + tid;
      int r = i >> 4, c4 = (i & 15) * 4;
      float4 qv = qpre[u];
      qv.x *= NORMV; qv.y *= NORMV; qv.z *= NORMV; qv.w *= NORMV;
      float4 hi, lo;
      hi.x = rnaf(qv.x); lo.x = qv.x - hi.x;
      hi.y = rnaf(qv.y); lo.y = qv.y - hi.y;
      hi.z = rnaf(qv.z); lo.z = qv.z - hi.z;
      hi.w = rnaf(qv.w); lo.w = qv.w - hi.w;
      *(float4*)&kq_hi[r * KQ_S + c4] = hi;
      *(float4*)&kq_lo[r * KQ_S + c4] = lo;
    }
    if (t < NTILES - 1) {
      qpre[0] = qb4[(t + 1) * 1024 + tid];
      qpre[1] = qb4[(t + 1) * 1024 + 512 + tid];
    }
    __syncthreads();

    if (tid < 64) {
      float s = 0.f;
#pragma unroll
      for (int d4 = 0; d4 < 16; d4++) {
        float4 h = *(const float4*)&kq_hi[tid * KQ_S + d4 * 4];
        float4 l = *(const float4*)&kq_lo[tid * KQ_S + d4 * 4];
        float x0 = h.x + l.x, x1 = h.y + l.y, x2 = h.z + l.z, x3 = h.w + l.w;
        s += x0 * x0 + x1 * x1 + x2 * x2 + x3 * x3;
      }
      diag_s[tid] = 0.5f * s;
    }

    // dash (B from registers)
    float dfrag[4][2][4];
#pragma unroll
    for (int g = 0; g < 4; g++)
#pragma unroll
      for (int mt = 0; mt < 2; mt++)
#pragma unroll
        for (int j = 0; j < 4; j++) dfrag[g][mt][j] = 0.f;

#pragma unroll
    for (int ks = 0; ks < 8; ks++) {
#pragma unroll
      for (int g = 0; g < 4; g++) {
        unsigned ah[4], al[4];
        ldsm4(ah, u_khi + (unsigned)(g * 16 * KQ_S + ks * 8 + aoKQ) * 4u);
        ldsm4(al, u_klo + (unsigned)(g * 16 * KQ_S + ks * 8 + aoKQ) * 4u);
        mma8(dfrag[g][0], ah, projB[ks]);
        mma8(dfrag[g][0], al, projB[ks]);
        mma8(dfrag[g][1], ah, projB[ks] + 2);
        mma8(dfrag[g][1], al, projB[ks] + 2);
      }
    }

    // per-warp row-max partials
#pragma unroll
    for (int g = 0; g < 4; g++) {
      float mlo = -1e30f, mhi = -1e30f;
#pragma unroll
      for (int mt = 0; mt < 2; mt++) {
        mlo = fmaxf(mlo, fmaxf(dfrag[g][mt][0], dfrag[g][mt][1]));
        mhi = fmaxf(mhi, fmaxf(dfrag[g][mt][2], dfrag[g][mt][3]));
      }
      mlo = fmaxf(mlo, __shfl_xor_sync(0xffffffffu, mlo, 1));
      mlo = fmaxf(mlo, __shfl_xor_sync(0xffffffffu, mlo, 2));
      mhi = fmaxf(mhi, __shfl_xor_sync(0xffffffffu, mhi, 1));
      mhi = fmaxf(mhi, __shfl_xor_sync(0xffffffffu, mhi, 2));
      if (tig == 0) {
        rmx[(g * 16 + gid) * 16 + wid] = mlo;
        rmx[(g * 16 + gid + 8) * 16 + wid] = mhi;
      }
    }
    __syncthreads();  // rmx + diag ready

    if (tid < 64) {
      float r0 = rmx[tid * 16];
#pragma unroll
      for (int w = 1; w < 16; w++) r0 = fmaxf(r0, rmx[tid * 16 + w]);
      sub_s[tid] = diag_s[tid] + r0;
    }
    __syncthreads();  // sub ready

    // q' = ratio*(exp(dash - sub) + eps) -> bufP (stride 268, float2);
    // denom partials folded in
#pragma unroll
    for (int g = 0; g < 4; g++) {
      int r = g * 16 + gid;
      float sub0 = sub_s[r], sub1 = sub_s[r + 8];
      float ds0 = 0.f, ds1 = 0.f;
#pragma unroll
      for (int mt = 0; mt < 2; mt++) {
        int m = m0 + mt * 8 + 2 * tig;
        float q0 = RATIO * (__expf(dfrag[g][mt][0] - sub0) + EPSV);
        float q1 = RATIO * (__expf(dfrag[g][mt][1] - sub0) + EPSV);
        float q2 = RATIO * (__expf(dfrag[g][mt][2] - sub1) + EPSV);
        float q3 = RATIO * (__expf(dfrag[g][mt][3] - sub1) + EPSV);
        ds0 += q0 * ksv[mt][0] + q1 * ksv[mt][1];
        ds1 += q2 * ksv[mt][0] + q3 * ksv[mt][1];
        *(float2*)&bufP[r * QP_S + m] = make_float2(rnaf(q0), rnaf(q1));
        *(float2*)&bufP[(r + 8) * QP_S + m] = make_float2(rnaf(q2), rnaf(q3));
      }
      ds0 += __shfl_xor_sync(0xffffffffu, ds0, 1);
      ds0 += __shfl_xor_sync(0xffffffffu, ds0, 2);
      ds1 += __shfl_xor_sync(0xffffffffu, ds1, 1);
      ds1 += __shfl_xor_sync(0xffffffffu, ds1, 2);
      if (tig == 0) {
        den[r * 16 + wid] = ds0;
        den[(r + 8) * 16 + wid] = ds1;
      }
    }
    __syncthreads();  // qp + den ready

    if (tid < 64) {
      float s = 0.f;
#pragma unroll
      for (int w = 0; w < 16; w++) s += den[tid * 16 + w];
      denom_s[tid] = s;
    }

    // out = q' @ ctx
    float ofrag[2][4];
#pragma unroll
    for (int et = 0; et < 2; et++)
#pragma unroll
      for (int j = 0; j < 4; j++) ofrag[et][j] = 0.f;

#pragma unroll 8
    for (int ks = 0; ks < 32; ks++) {
      unsigned a[4], b[4];
      ldsm4(a, u_P + (unsigned)(rg * QP_S + ks * 8 + aoQP) * 4u);
      ldsm4(b, u_C + (unsigned)(eh * CT_S + ks * 8 + boCT) * 4u);
      mma8(ofrag[0], a, b);
      mma8(ofrag[1], a, b + 2);
    }
    __syncthreads();  // denom ready

    float inv0 = 1.f / denom_s[rg + gid];
    float inv1 = 1.f / denom_s[rg + gid + 8];
    float* ob = outg + ((size_t)bh * Nn + (size_t)t * 64) * Dn;
#pragma unroll
    for (int et = 0; et < 2; et++) {
      int e = eh + et * 8 + 2 * tig;
      int r = rg + gid;
      *(float2*)&ob[r * Dn + e] =
          make_float2(ofrag[et][0] * inv0, ofrag[et][1] * inv0);
      *(float2*)&ob[(r + 8) * Dn + e] =
          make_float2(ofrag[et][2] * inv1, ofrag[et][3] * inv1);
    }
  }
}

// ---------------------------------------------------------------------------
extern "C" void kernel_launch(void* const* d_in, const int* in_sizes, int n_in,
                              void* d_out, int out_size) {
  const float* q    = (const float*)d_in[0];
  const float* k    = (const float*)d_in[1];
  const float* v    = (const float*)d_in[2];
  const float* proj = (const float*)d_in[3];
  float* out = (float*)d_out;

  const int smem =
      (17408 + 17152 + 4352 + 4352 + 4352 + 64 + 64 + 32 + 256 + 64 + 1024 +
       1024 + 64) * 4;

  cudaFuncSetAttribute(fused_kernel, cudaFuncAttributeMaxDynamicSharedMemorySize, smem);
  fused_kernel<<<BHn, 512, smem>>>(q, k, v, proj, out);
}